// round 11
// baseline (speedup 1.0000x reference)
#include <cuda_runtime.h>
#include <cuda_bf16.h>
#include <cstdint>

// ============================================================================
// PNeRF coordinate extension as a chunked affine prefix scan (round 11).
// State (M, t): x_world = x_local @ M + t.  Step: M' = S M ; t' = t + bl*M'[0]
// Round 11: single-walk design. k1 walks once, saving per-atom LOCAL
//   translations to scratch; k3 applies the chunk prefix as a 3x3 matvec
//   per atom (no trig, no chain). R6 tile layout throughout.
// ============================================================================

#define C1    16                 // atoms per chunk (per thread)
#define TPB   192                // chunks per block (6 warps)
#define NW    (TPB/32)
#define Q     (3*C1)             // 48 floats per chunk
#define ROWF  52                 // padded floats per row (208B, conflict-free .128)
#define ROW4  13                 // float4 per row
#define TILE_F (TPB*C1*3)        // 9216 floats per block tile
#define MAXCHUNKS 188160
#define MAXBLK    1024

struct Aff { float m[9]; float t[3]; };

__device__ float  g_cs[12 * MAXCHUNKS];         // chunkScan, SoA: [comp][chunk]
__device__ float  g_blockComp[MAXBLK * 12];
__device__ float  g_basePrefix[MAXBLK * 12];
__device__ float4 g_scratch4[MAXCHUNKS * ROW4]; // per-chunk padded local-t rows

// ---------------------------------------------------------------------------
// Accurate fp32 sincos (immune to --use_fast_math): Cody-Waite + Cephes polys.
// ---------------------------------------------------------------------------
__device__ __forceinline__ void fsincos(float x, float& s, float& c) {
    float q = rintf(x * 0.6366197723675814f);
    float r = fmaf(q, -1.5707963705062866f, x);
    r = fmaf(q, 4.37113883e-8f, r);
    int iq = (int)q;
    float z = r * r;
    float ps = fmaf(z, -1.9515295891e-4f, 8.3321608736e-3f);
    ps = fmaf(z, ps, -1.6666654611e-1f);
    float sr = fmaf(r * z, ps, r);
    float pc = fmaf(z, 2.443315711809948e-5f, -1.388731625493765e-3f);
    pc = fmaf(z, pc, 4.166664568298827e-2f);
    float cr = fmaf(z * z, pc, fmaf(z, -0.5f, 1.0f));
    bool sw = (iq & 1);
    float ss = sw ? cr : sr;
    float cc = sw ? sr : cr;
    if (iq & 2)        ss = -ss;
    if ((iq + 1) & 2)  cc = -cc;
    s = ss; c = cc;
}

// Theta path: bond_angle in [1.9, 2.1] -> Cody-Waite quadrant is always 1.
__device__ __forceinline__ void fsincos_th(float x, float& s, float& c) {
    float r = (x - 1.5707963705062866f) + 4.37113883e-8f;
    float z = r * r;
    float ps = fmaf(z, -1.9515295891e-4f, 8.3321608736e-3f);
    ps = fmaf(z, ps, -1.6666654611e-1f);
    float sr = fmaf(r * z, ps, r);
    float pc = fmaf(z, 2.443315711809948e-5f, -1.388731625493765e-3f);
    pc = fmaf(z, pc, 4.166664568298827e-2f);
    float cr = fmaf(z * z, pc, fmaf(z, -0.5f, 1.0f));
    s = cr; c = -sr;
}

__device__ __forceinline__ Aff aff_identity() {
    Aff a = {{1,0,0, 0,1,0, 0,0,1}, {0,0,0}};
    return a;
}

// Combine: A earlier (or state), B later composite.
__device__ __forceinline__ Aff cmb(const Aff& A, const Aff& B) {
    Aff r;
#pragma unroll
    for (int i = 0; i < 3; i++) {
        float b0 = B.m[3*i], b1 = B.m[3*i+1], b2 = B.m[3*i+2];
#pragma unroll
        for (int j = 0; j < 3; j++)
            r.m[3*i+j] = fmaf(b0, A.m[j], fmaf(b1, A.m[3+j], b2 * A.m[6+j]));
    }
#pragma unroll
    for (int j = 0; j < 3; j++)
        r.t[j] = fmaf(B.t[0], A.m[j], fmaf(B.t[1], A.m[3+j],
                 fmaf(B.t[2], A.m[6+j], A.t[j])));
    return r;
}

__device__ __forceinline__ void chain_step(float bl, float th, float ph, Aff& s) {
    float st, ct, sp, cp;
    fsincos_th(th, st, ct);
    fsincos(ph, sp, cp);
    float a = cp * st, b = sp * st, c = cp * ct, d = sp * ct;
#pragma unroll
    for (int j = 0; j < 3; j++) {
        float m0 = s.m[j], m1 = s.m[3+j], m2 = s.m[6+j];
        float r0 = fmaf(ct, m0, fmaf(a, m1, b * m2));
        float r1 = fmaf(c,  m1, fmaf(d, m2, -st * m0));
        float r2 = fmaf(cp, m2, -sp * m1);
        s.m[j] = r0; s.m[3+j] = r1; s.m[6+j] = r2;
        s.t[j] = fmaf(bl, r0, s.t[j]);
    }
}

// First step from identity: s = S, t = bl*S[0].
__device__ __forceinline__ void first_step(float bl, float th, float ph, Aff& s) {
    float st, ct, sp, cp;
    fsincos_th(th, st, ct);
    fsincos(ph, sp, cp);
    s.m[0] = ct;        s.m[1] = cp*st;  s.m[2] = sp*st;
    s.m[3] = -st;       s.m[4] = cp*ct;  s.m[5] = sp*ct;
    s.m[6] = 0.0f;      s.m[7] = -sp;    s.m[8] = cp;
    s.t[0] = bl*s.m[0]; s.t[1] = bl*s.m[1]; s.t[2] = bl*s.m[2];
}

__device__ __forceinline__ void reortho(Aff& s) {
    float inv = rsqrtf(fmaf(s.m[0], s.m[0], fmaf(s.m[1], s.m[1], s.m[2]*s.m[2])));
    s.m[0] *= inv; s.m[1] *= inv; s.m[2] *= inv;
    float d = fmaf(s.m[6], s.m[0], fmaf(s.m[7], s.m[1], s.m[8]*s.m[2]));
    s.m[6] = fmaf(-d, s.m[0], s.m[6]);
    s.m[7] = fmaf(-d, s.m[1], s.m[7]);
    s.m[8] = fmaf(-d, s.m[2], s.m[8]);
    inv = rsqrtf(fmaf(s.m[6], s.m[6], fmaf(s.m[7], s.m[7], s.m[8]*s.m[8])));
    s.m[6] *= inv; s.m[7] *= inv; s.m[8] *= inv;
    s.m[3] = s.m[7]*s.m[2] - s.m[8]*s.m[1];
    s.m[4] = s.m[8]*s.m[0] - s.m[6]*s.m[2];
    s.m[5] = s.m[6]*s.m[1] - s.m[7]*s.m[0];
}

__device__ __forceinline__ void aff_store(float* p, const Aff& a) {
#pragma unroll
    for (int i = 0; i < 9; i++) p[i] = a.m[i];
#pragma unroll
    for (int i = 0; i < 3; i++) p[9+i] = a.t[i];
}
__device__ __forceinline__ Aff aff_load(const float* p) {
    Aff a;
#pragma unroll
    for (int i = 0; i < 9; i++) a.m[i] = p[i];
#pragma unroll
    for (int i = 0; i < 3; i++) a.t[i] = p[9+i];
    return a;
}

__device__ __forceinline__ Aff aff_shfl_up(const Aff& a, int delta) {
    Aff r;
#pragma unroll
    for (int i = 0; i < 9; i++) r.m[i] = __shfl_up_sync(0xffffffffu, a.m[i], delta);
#pragma unroll
    for (int i = 0; i < 3; i++) r.t[i] = __shfl_up_sync(0xffffffffu, a.t[i], delta);
    return r;
}

// Stage a block tile into padded linear rows: st[(f/Q)*ROWF + f%Q].
__device__ __forceinline__ void stage_in(float* st, const float* __restrict__ gin,
                                          int nfl, int tid) {
    if (nfl == TILE_F) {
        const float4* g4 = (const float4*)gin;
        float4* s4 = (float4*)st;
        int j0 = tid / 12, k0 = tid - 12 * (tid / 12);
        int dst = j0 * ROW4 + k0;
#pragma unroll
        for (int it = 0; it < TILE_F/4/TPB; it++) {     // 12
            s4[dst] = g4[tid + it*TPB];
            dst += 16 * ROW4;
        }
    } else {
        int q0 = tid % Q, j0 = tid / Q;
        for (int f = tid; f < nfl; f += TPB) {
            st[j0*ROWF + q0] = gin[f];
            j0 += TPB/Q;
        }
    }
}

// ---------------------------------------------------------------------------
// K1: stage, vector walk WITH in-place local-t write-back, block scan, SoA
//     chunk-scan stores, then flush padded tile to scratch (straight copy).
// ---------------------------------------------------------------------------
__global__ void __launch_bounds__(TPB) k1_chunks(const float* __restrict__ inner,
                                                 int n, int nchunks) {
    __shared__ float st[TPB * ROWF];    // 39936 B
    __shared__ float swc[NW * 12];
    int tid = threadIdx.x, b = blockIdx.x;
    int lane = tid & 31, wid = tid >> 5;
    int chunk = b * TPB + tid;

    long long tile0 = (long long)b * TILE_F;
    int nfl = (int)min((long long)TILE_F, (long long)n * 3 - tile0);
    stage_in(st, inner + tile0, nfl, tid);
    __syncthreads();

    Aff s = aff_identity();
    if (chunk < nchunks) {
        int base = chunk * C1;
        if (base + C1 <= n) {
            float4* row4 = (float4*)st + tid * ROW4;
#pragma unroll
            for (int G = 0; G < 4; G++) {
                float4 va = row4[3*G], vb = row4[3*G+1], vc = row4[3*G+2];
                float4 oa, ob, oc;
                if (G == 0) first_step(va.x, va.y, va.z, s);
                else        chain_step(va.x, va.y, va.z, s);
                oa.x=s.t[0]; oa.y=s.t[1]; oa.z=s.t[2];
                chain_step(va.w, vb.x, vb.y, s); oa.w=s.t[0]; ob.x=s.t[1]; ob.y=s.t[2];
                chain_step(vb.z, vb.w, vc.x, s); ob.z=s.t[0]; ob.w=s.t[1]; oc.x=s.t[2];
                chain_step(vc.y, vc.z, vc.w, s); oc.y=s.t[0]; oc.z=s.t[1]; oc.w=s.t[2];
                row4[3*G] = oa; row4[3*G+1] = ob; row4[3*G+2] = oc;
            }
        } else {
            int lim = n - base;
            float* col = st + tid * ROWF;
            for (int k = 0; k < lim; k++) {
                if (k == 0) first_step(col[0], col[1], col[2], s);
                else        chain_step(col[3*k], col[3*k+1], col[3*k+2], s);
                col[3*k]   = s.t[0];
                col[3*k+1] = s.t[1];
                col[3*k+2] = s.t[2];
            }
        }
    }
    // block scan (warp shuffle + cross-warp)
#pragma unroll
    for (int off = 1; off < 32; off <<= 1) {
        Aff p = aff_shfl_up(s, off);
        if (lane >= off) s = cmb(p, s);
    }
    if (lane == 31) aff_store(&swc[wid*12], s);
    __syncthreads();
    if (wid == 0) {
        Aff w = (lane < NW) ? aff_load(&swc[lane*12]) : aff_identity();
#pragma unroll
        for (int off = 1; off < NW; off <<= 1) {
            Aff p = aff_shfl_up(w, off);
            if (lane >= off) w = cmb(p, w);
        }
        if (lane < NW) aff_store(&swc[lane*12], w);
    }
    __syncthreads();
    if (wid > 0) s = cmb(aff_load(&swc[(wid-1)*12]), s);

    if (chunk < nchunks) {
#pragma unroll
        for (int c = 0; c < 9; c++)  g_cs[c*MAXCHUNKS + chunk] = s.m[c];
#pragma unroll
        for (int c = 0; c < 3; c++)  g_cs[(9+c)*MAXCHUNKS + chunk] = s.t[c];
    }
    if (tid == TPB - 1) aff_store(&g_blockComp[b*12], s);

    // flush padded local-t tile to scratch (straight float4 copy; walk writes
    // were ordered before the scan's first __syncthreads)
    float4* gs4 = g_scratch4 + (long long)b * (TPB * ROW4);
    const float4* s4 = (const float4*)st;
#pragma unroll
    for (int it = 0; it < ROW4; it++)      // 13 * 192 = 2496
        gs4[tid + it*TPB] = s4[tid + it*TPB];
}

// ---------------------------------------------------------------------------
// K2: scan block composites (hierarchical shuffle), seed with mainchain frame.
// ---------------------------------------------------------------------------
__global__ void __launch_bounds__(1024) k2_scan(int nb, const float* __restrict__ mc,
                                                float* __restrict__ out) {
    __shared__ float swc[32 * 12];
    __shared__ float s0sh[12];
    int tid = threadIdx.x, lane = tid & 31, wid = tid >> 5;
    if (tid == 0) {
        float Ax = mc[0], Ay = mc[1], Az = mc[2];
        float Bx = mc[3], By = mc[4], Bz = mc[5];
        float Cx = mc[6], Cy = mc[7], Cz = mc[8];
        float bx = Cx-Bx, by = Cy-By, bz = Cz-Bz;
        float inv = rsqrtf(bx*bx + by*by + bz*bz);
        bx *= inv; by *= inv; bz *= inv;
        float ux = Bx-Ax, uy = By-Ay, uz = Bz-Az;
        float nx = uy*bz - uz*by, ny = uz*bx - ux*bz, nz = ux*by - uy*bx;
        inv = rsqrtf(nx*nx + ny*ny + nz*nz);
        nx *= inv; ny *= inv; nz *= inv;
        s0sh[0]=bx; s0sh[1]=by; s0sh[2]=bz;
        s0sh[3]=ny*bz - nz*by; s0sh[4]=nz*bx - nx*bz; s0sh[5]=nx*by - ny*bx;
        s0sh[6]=nx; s0sh[7]=ny; s0sh[8]=nz;
        s0sh[9]=Cx; s0sh[10]=Cy; s0sh[11]=Cz;
    }
    if (tid < 9) out[tid] = mc[tid];
    Aff s = (tid < nb) ? aff_load(&g_blockComp[tid*12]) : aff_identity();
#pragma unroll
    for (int off = 1; off < 32; off <<= 1) {
        Aff p = aff_shfl_up(s, off);
        if (lane >= off) s = cmb(p, s);
    }
    if (lane == 31) aff_store(&swc[wid*12], s);
    __syncthreads();
    if (wid == 0) {
        Aff w = aff_load(&swc[lane*12]);
#pragma unroll
        for (int off = 1; off < 32; off <<= 1) {
            Aff p = aff_shfl_up(w, off);
            if (lane >= off) w = cmb(p, w);
        }
        aff_store(&swc[lane*12], w);
    }
    __syncthreads();
    if (wid > 0) s = cmb(aff_load(&swc[(wid-1)*12]), s);  // full inclusive
    Aff e = aff_shfl_up(s, 1);                             // exclusive prefix
    if (lane == 0 && wid > 0) e = aff_load(&swc[(wid-1)*12]);
    if (tid < nb) {
        Aff s0 = aff_load(s0sh);
        Aff bp = (tid == 0) ? s0 : cmb(s0, e);
        reortho(bp);
        aff_store(&g_basePrefix[tid*12], bp);
    }
}

// ---------------------------------------------------------------------------
// K3: copy scratch tile to smem, apply chunk prefix as 3x3 matvec per atom
//     (NO trig, NO chain), flush coalesced to out.
// ---------------------------------------------------------------------------
__global__ void __launch_bounds__(TPB) k3_emit(int n, int nchunks,
                                               float* __restrict__ out) {
    __shared__ float st[TPB * ROWF];
    int tid = threadIdx.x, b = blockIdx.x;
    int chunk = b * TPB + tid;

    long long tile0 = (long long)b * TILE_F;
    int nfl = (int)min((long long)TILE_F, (long long)n * 3 - tile0);

    // stage scratch tile (straight float4 copy)
    {
        const float4* gs4 = g_scratch4 + (long long)b * (TPB * ROW4);
        float4* s4 = (float4*)st;
#pragma unroll
        for (int it = 0; it < ROW4; it++)
            s4[tid + it*TPB] = gs4[tid + it*TPB];
    }
    __syncthreads();

    if (chunk < nchunks) {
        Aff s = aff_load(&g_basePrefix[b*12]);
        if (tid > 0) {
            Aff pre;
#pragma unroll
            for (int c = 0; c < 9; c++) pre.m[c] = g_cs[c*MAXCHUNKS + chunk - 1];
#pragma unroll
            for (int c = 0; c < 3; c++) pre.t[c] = g_cs[(9+c)*MAXCHUNKS + chunk - 1];
            s = cmb(s, pre);
        }
        reortho(s);
        // glob_j = lx*m[j] + ly*m[3+j] + lz*m[6+j] + t[j]
        int base = chunk * C1;
        if (base + C1 <= n) {
            float4* row4 = (float4*)st + tid * ROW4;
#pragma unroll
            for (int G = 0; G < 4; G++) {
                float4 va = row4[3*G], vb = row4[3*G+1], vc = row4[3*G+2];
                float4 oa, ob, oc;
#define XFORM(LX, LY, LZ, O0, O1, O2) \
                O0 = fmaf(LX, s.m[0], fmaf(LY, s.m[3], fmaf(LZ, s.m[6], s.t[0]))); \
                O1 = fmaf(LX, s.m[1], fmaf(LY, s.m[4], fmaf(LZ, s.m[7], s.t[1]))); \
                O2 = fmaf(LX, s.m[2], fmaf(LY, s.m[5], fmaf(LZ, s.m[8], s.t[2])));
                XFORM(va.x, va.y, va.z, oa.x, oa.y, oa.z)
                XFORM(va.w, vb.x, vb.y, oa.w, ob.x, ob.y)
                XFORM(vb.z, vb.w, vc.x, ob.z, ob.w, oc.x)
                XFORM(vc.y, vc.z, vc.w, oc.y, oc.z, oc.w)
#undef XFORM
                row4[3*G] = oa; row4[3*G+1] = ob; row4[3*G+2] = oc;
            }
        } else {
            int lim = n - base;
            float* col = st + tid * ROWF;
            for (int k = 0; k < lim; k++) {
                float lx = col[3*k], ly = col[3*k+1], lz = col[3*k+2];
                col[3*k]   = fmaf(lx, s.m[0], fmaf(ly, s.m[3], fmaf(lz, s.m[6], s.t[0])));
                col[3*k+1] = fmaf(lx, s.m[1], fmaf(ly, s.m[4], fmaf(lz, s.m[7], s.t[1])));
                col[3*k+2] = fmaf(lx, s.m[2], fmaf(ly, s.m[5], fmaf(lz, s.m[8], s.t[2])));
            }
        }
    }
    __syncthreads();
    // coalesced scalar flush; q invariant across iterations (TPB % Q == 0)
    float* gout = out + 9 + tile0;
    int q0 = tid % Q, j0 = tid / Q;
#pragma unroll 8
    for (int f = tid; f < nfl; f += TPB) {
        gout[f] = st[j0*ROWF + q0];
        j0 += TPB/Q;
    }
}

extern "C" void kernel_launch(void* const* d_in, const int* in_sizes, int n_in,
                              void* d_out, int out_size) {
    const float* inner = (const float*)d_in[0];
    const float* mc    = (const float*)d_in[2];
    float* out = (float*)d_out;
    int n = in_sizes[0] / 3;
    int nchunks = (n + C1 - 1) / C1;              // 187500
    int nblocks = (nchunks + TPB - 1) / TPB;      // 977  (<= 1024)

    k1_chunks<<<nblocks, TPB>>>(inner, n, nchunks);
    k2_scan<<<1, 1024>>>(nblocks, mc, out);
    k3_emit<<<nblocks, TPB>>>(n, nchunks, out);
}

// round 12
// speedup vs baseline: 1.1291x; 1.1291x over previous
#include <cuda_runtime.h>
#include <cuda_bf16.h>
#include <cstdint>

// ============================================================================
// PNeRF coordinate extension as a chunked affine prefix scan (round 12).
// State (M, t): x_world = x_local @ M + t.  Step: M' = S M ; t' = t + bl*M'[0]
// Round 12 = proven R6 structure + (a) Givens-factored step S = Rz(th)*Rx(ph)
//            (fewer instr/step, exact algebra), (b) division-free float4
//            flush in k3.
// ============================================================================

#define C1    16                 // atoms per chunk (per thread)
#define TPB   192                // chunks per block (6 warps)
#define NW    (TPB/32)
#define Q     (3*C1)             // 48 floats per chunk
#define ROWF  52                 // padded floats per row (208B, conflict-free .128)
#define ROW4  13                 // float4 per row
#define TILE_F (TPB*C1*3)        // 9216 floats per block tile
#define MAXCHUNKS 188160
#define MAXBLK    1024

struct Aff { float m[9]; float t[3]; };

__device__ float g_cs[12 * MAXCHUNKS];          // chunkScan, SoA: [comp][chunk]
__device__ float g_blockComp[MAXBLK * 12];
__device__ float g_basePrefix[MAXBLK * 12];

// ---------------------------------------------------------------------------
// Accurate fp32 sincos (immune to --use_fast_math): Cody-Waite + Cephes polys.
// ---------------------------------------------------------------------------
__device__ __forceinline__ void fsincos(float x, float& s, float& c) {
    float q = rintf(x * 0.6366197723675814f);
    float r = fmaf(q, -1.5707963705062866f, x);
    r = fmaf(q, 4.37113883e-8f, r);
    int iq = (int)q;
    float z = r * r;
    float ps = fmaf(z, -1.9515295891e-4f, 8.3321608736e-3f);
    ps = fmaf(z, ps, -1.6666654611e-1f);
    float sr = fmaf(r * z, ps, r);
    float pc = fmaf(z, 2.443315711809948e-5f, -1.388731625493765e-3f);
    pc = fmaf(z, pc, 4.166664568298827e-2f);
    float cr = fmaf(z * z, pc, fmaf(z, -0.5f, 1.0f));
    bool sw = (iq & 1);
    float ss = sw ? cr : sr;
    float cc = sw ? sr : cr;
    if (iq & 2)        ss = -ss;
    if ((iq + 1) & 2)  cc = -cc;
    s = ss; c = cc;
}

// Theta path: bond_angle in [1.9, 2.1] -> Cody-Waite quadrant is always 1.
__device__ __forceinline__ void fsincos_th(float x, float& s, float& c) {
    float r = (x - 1.5707963705062866f) + 4.37113883e-8f;
    float z = r * r;
    float ps = fmaf(z, -1.9515295891e-4f, 8.3321608736e-3f);
    ps = fmaf(z, ps, -1.6666654611e-1f);
    float sr = fmaf(r * z, ps, r);
    float pc = fmaf(z, 2.443315711809948e-5f, -1.388731625493765e-3f);
    pc = fmaf(z, pc, 4.166664568298827e-2f);
    float cr = fmaf(z * z, pc, fmaf(z, -0.5f, 1.0f));
    s = cr; c = -sr;
}

__device__ __forceinline__ Aff aff_identity() {
    Aff a = {{1,0,0, 0,1,0, 0,0,1}, {0,0,0}};
    return a;
}

// Combine: A earlier (or state), B later composite.
__device__ __forceinline__ Aff cmb(const Aff& A, const Aff& B) {
    Aff r;
#pragma unroll
    for (int i = 0; i < 3; i++) {
        float b0 = B.m[3*i], b1 = B.m[3*i+1], b2 = B.m[3*i+2];
#pragma unroll
        for (int j = 0; j < 3; j++)
            r.m[3*i+j] = fmaf(b0, A.m[j], fmaf(b1, A.m[3+j], b2 * A.m[6+j]));
    }
#pragma unroll
    for (int j = 0; j < 3; j++)
        r.t[j] = fmaf(B.t[0], A.m[j], fmaf(B.t[1], A.m[3+j],
                 fmaf(B.t[2], A.m[6+j], A.t[j])));
    return r;
}

// Givens-factored step: S = Rz(th) * Rx(ph), applied column-wise.
// Rx: u = cp*m1 + sp*m2 ; v = cp*m2 - sp*m1
// Rz: r0 = ct*m0 + st*u ; r1 = ct*u - st*m0 ; r2 = v
__device__ __forceinline__ void chain_step(float bl, float th, float ph, Aff& s) {
    float st, ct, sp, cp;
    fsincos_th(th, st, ct);
    fsincos(ph, sp, cp);
#pragma unroll
    for (int j = 0; j < 3; j++) {
        float m0 = s.m[j], m1 = s.m[3+j], m2 = s.m[6+j];
        float u  = fmaf(cp, m1, sp * m2);
        float v  = fmaf(cp, m2, -sp * m1);
        float r0 = fmaf(ct, m0, st * u);
        float r1 = fmaf(ct, u, -st * m0);
        s.m[j] = r0; s.m[3+j] = r1; s.m[6+j] = v;
        s.t[j] = fmaf(bl, r0, s.t[j]);
    }
}

// First step from identity: s = S, t = bl*S[0].
__device__ __forceinline__ void first_step(float bl, float th, float ph, Aff& s) {
    float st, ct, sp, cp;
    fsincos_th(th, st, ct);
    fsincos(ph, sp, cp);
    s.m[0] = ct;        s.m[1] = cp*st;  s.m[2] = sp*st;
    s.m[3] = -st;       s.m[4] = cp*ct;  s.m[5] = sp*ct;
    s.m[6] = 0.0f;      s.m[7] = -sp;    s.m[8] = cp;
    s.t[0] = bl*s.m[0]; s.t[1] = bl*s.m[1]; s.t[2] = bl*s.m[2];
}

__device__ __forceinline__ void reortho(Aff& s) {
    float inv = rsqrtf(fmaf(s.m[0], s.m[0], fmaf(s.m[1], s.m[1], s.m[2]*s.m[2])));
    s.m[0] *= inv; s.m[1] *= inv; s.m[2] *= inv;
    float d = fmaf(s.m[6], s.m[0], fmaf(s.m[7], s.m[1], s.m[8]*s.m[2]));
    s.m[6] = fmaf(-d, s.m[0], s.m[6]);
    s.m[7] = fmaf(-d, s.m[1], s.m[7]);
    s.m[8] = fmaf(-d, s.m[2], s.m[8]);
    inv = rsqrtf(fmaf(s.m[6], s.m[6], fmaf(s.m[7], s.m[7], s.m[8]*s.m[8])));
    s.m[6] *= inv; s.m[7] *= inv; s.m[8] *= inv;
    s.m[3] = s.m[7]*s.m[2] - s.m[8]*s.m[1];
    s.m[4] = s.m[8]*s.m[0] - s.m[6]*s.m[2];
    s.m[5] = s.m[6]*s.m[1] - s.m[7]*s.m[0];
}

__device__ __forceinline__ void aff_store(float* p, const Aff& a) {
#pragma unroll
    for (int i = 0; i < 9; i++) p[i] = a.m[i];
#pragma unroll
    for (int i = 0; i < 3; i++) p[9+i] = a.t[i];
}
__device__ __forceinline__ Aff aff_load(const float* p) {
    Aff a;
#pragma unroll
    for (int i = 0; i < 9; i++) a.m[i] = p[i];
#pragma unroll
    for (int i = 0; i < 3; i++) a.t[i] = p[9+i];
    return a;
}

__device__ __forceinline__ Aff aff_shfl_up(const Aff& a, int delta) {
    Aff r;
#pragma unroll
    for (int i = 0; i < 9; i++) r.m[i] = __shfl_up_sync(0xffffffffu, a.m[i], delta);
#pragma unroll
    for (int i = 0; i < 3; i++) r.t[i] = __shfl_up_sync(0xffffffffu, a.t[i], delta);
    return r;
}

// Stage a block tile into padded linear rows: st[(f/Q)*ROWF + f%Q].
__device__ __forceinline__ void stage_in(float* st, const float* __restrict__ gin,
                                          int nfl, int tid) {
    if (nfl == TILE_F) {
        const float4* g4 = (const float4*)gin;
        float4* s4 = (float4*)st;
        int j0 = tid / 12, k0 = tid - 12 * (tid / 12);
        int dst = j0 * ROW4 + k0;
#pragma unroll
        for (int it = 0; it < TILE_F/4/TPB; it++) {     // 12
            s4[dst] = g4[tid + it*TPB];
            dst += 16 * ROW4;
        }
    } else {
        int q0 = tid % Q, j0 = tid / Q;
        for (int f = tid; f < nfl; f += TPB) {
            st[j0*ROWF + q0] = gin[f];
            j0 += TPB/Q;
        }
    }
}

// ---------------------------------------------------------------------------
// K1: stage tile, per-chunk composites (vector walk), block scan, SoA stores.
// ---------------------------------------------------------------------------
__global__ void __launch_bounds__(TPB) k1_chunks(const float* __restrict__ inner,
                                                 int n, int nchunks) {
    __shared__ float st[TPB * ROWF];    // 39936 B
    __shared__ float swc[NW * 12];
    int tid = threadIdx.x, b = blockIdx.x;
    int lane = tid & 31, wid = tid >> 5;
    int chunk = b * TPB + tid;

    long long tile0 = (long long)b * TILE_F;
    int nfl = (int)min((long long)TILE_F, (long long)n * 3 - tile0);
    stage_in(st, inner + tile0, nfl, tid);
    __syncthreads();

    Aff s = aff_identity();
    if (chunk < nchunks) {
        int base = chunk * C1;
        if (base + C1 <= n) {
            const float4* row4 = (const float4*)st + tid * ROW4;
            float4 va = row4[0], vb = row4[1], vc = row4[2];
            first_step(va.x, va.y, va.z, s);
            chain_step(va.w, vb.x, vb.y, s);
            chain_step(vb.z, vb.w, vc.x, s);
            chain_step(vc.y, vc.z, vc.w, s);
#pragma unroll
            for (int G = 1; G < 4; G++) {
                va = row4[3*G]; vb = row4[3*G+1]; vc = row4[3*G+2];
                chain_step(va.x, va.y, va.z, s);
                chain_step(va.w, vb.x, vb.y, s);
                chain_step(vb.z, vb.w, vc.x, s);
                chain_step(vc.y, vc.z, vc.w, s);
            }
        } else {
            int lim = n - base;
            const float* col = st + tid * ROWF;
            if (lim > 0) first_step(col[0], col[1], col[2], s);
            for (int k = 1; k < lim; k++)
                chain_step(col[3*k], col[3*k+1], col[3*k+2], s);
        }
    }
    // block scan (warp shuffle + cross-warp)
#pragma unroll
    for (int off = 1; off < 32; off <<= 1) {
        Aff p = aff_shfl_up(s, off);
        if (lane >= off) s = cmb(p, s);
    }
    if (lane == 31) aff_store(&swc[wid*12], s);
    __syncthreads();
    if (wid == 0) {
        Aff w = (lane < NW) ? aff_load(&swc[lane*12]) : aff_identity();
#pragma unroll
        for (int off = 1; off < NW; off <<= 1) {
            Aff p = aff_shfl_up(w, off);
            if (lane >= off) w = cmb(p, w);
        }
        if (lane < NW) aff_store(&swc[lane*12], w);
    }
    __syncthreads();
    if (wid > 0) s = cmb(aff_load(&swc[(wid-1)*12]), s);

    if (chunk < nchunks) {
#pragma unroll
        for (int c = 0; c < 9; c++)  g_cs[c*MAXCHUNKS + chunk] = s.m[c];
#pragma unroll
        for (int c = 0; c < 3; c++)  g_cs[(9+c)*MAXCHUNKS + chunk] = s.t[c];
    }
    if (tid == TPB - 1) aff_store(&g_blockComp[b*12], s);
}

// ---------------------------------------------------------------------------
// K2: scan block composites (hierarchical shuffle), seed with mainchain frame.
// ---------------------------------------------------------------------------
__global__ void __launch_bounds__(1024) k2_scan(int nb, const float* __restrict__ mc,
                                                float* __restrict__ out) {
    __shared__ float swc[32 * 12];
    __shared__ float s0sh[12];
    int tid = threadIdx.x, lane = tid & 31, wid = tid >> 5;
    if (tid == 0) {
        float Ax = mc[0], Ay = mc[1], Az = mc[2];
        float Bx = mc[3], By = mc[4], Bz = mc[5];
        float Cx = mc[6], Cy = mc[7], Cz = mc[8];
        float bx = Cx-Bx, by = Cy-By, bz = Cz-Bz;
        float inv = rsqrtf(bx*bx + by*by + bz*bz);
        bx *= inv; by *= inv; bz *= inv;
        float ux = Bx-Ax, uy = By-Ay, uz = Bz-Az;
        float nx = uy*bz - uz*by, ny = uz*bx - ux*bz, nz = ux*by - uy*bx;
        inv = rsqrtf(nx*nx + ny*ny + nz*nz);
        nx *= inv; ny *= inv; nz *= inv;
        s0sh[0]=bx; s0sh[1]=by; s0sh[2]=bz;
        s0sh[3]=ny*bz - nz*by; s0sh[4]=nz*bx - nx*bz; s0sh[5]=nx*by - ny*bx;
        s0sh[6]=nx; s0sh[7]=ny; s0sh[8]=nz;
        s0sh[9]=Cx; s0sh[10]=Cy; s0sh[11]=Cz;
    }
    if (tid < 9) out[tid] = mc[tid];
    Aff s = (tid < nb) ? aff_load(&g_blockComp[tid*12]) : aff_identity();
#pragma unroll
    for (int off = 1; off < 32; off <<= 1) {
        Aff p = aff_shfl_up(s, off);
        if (lane >= off) s = cmb(p, s);
    }
    if (lane == 31) aff_store(&swc[wid*12], s);
    __syncthreads();
    if (wid == 0) {
        Aff w = aff_load(&swc[lane*12]);   // 32 warps present in this kernel
#pragma unroll
        for (int off = 1; off < 32; off <<= 1) {
            Aff p = aff_shfl_up(w, off);
            if (lane >= off) w = cmb(p, w);
        }
        aff_store(&swc[lane*12], w);
    }
    __syncthreads();
    if (wid > 0) s = cmb(aff_load(&swc[(wid-1)*12]), s);  // full inclusive
    Aff e = aff_shfl_up(s, 1);                             // exclusive prefix
    if (lane == 0 && wid > 0) e = aff_load(&swc[(wid-1)*12]);
    if (tid < nb) {
        Aff s0 = aff_load(s0sh);
        Aff bp = (tid == 0) ? s0 : cmb(s0, e);
        reortho(bp);
        aff_store(&g_basePrefix[tid*12], bp);
    }
}

// ---------------------------------------------------------------------------
// K3: stage, seed from prefix, vector walk with in-place float4 write-back,
//     division-free vectorized flush (invariant q0; 768 = 16*48).
// ---------------------------------------------------------------------------
__global__ void __launch_bounds__(TPB) k3_emit(const float* __restrict__ inner,
                                               int n, int nchunks,
                                               float* __restrict__ out) {
    __shared__ float st[TPB * ROWF];
    int tid = threadIdx.x, b = blockIdx.x;
    int chunk = b * TPB + tid;

    long long tile0 = (long long)b * TILE_F;
    int nfl = (int)min((long long)TILE_F, (long long)n * 3 - tile0);
    stage_in(st, inner + tile0, nfl, tid);
    __syncthreads();

    if (chunk < nchunks) {
        Aff s = aff_load(&g_basePrefix[b*12]);
        if (tid > 0) {
            Aff pre;
#pragma unroll
            for (int c = 0; c < 9; c++) pre.m[c] = g_cs[c*MAXCHUNKS + chunk - 1];
#pragma unroll
            for (int c = 0; c < 3; c++) pre.t[c] = g_cs[(9+c)*MAXCHUNKS + chunk - 1];
            s = cmb(s, pre);
        }
        reortho(s);
        int base = chunk * C1;
        if (base + C1 <= n) {
            float4* row4 = (float4*)st + tid * ROW4;
#pragma unroll
            for (int G = 0; G < 4; G++) {
                float4 va = row4[3*G], vb = row4[3*G+1], vc = row4[3*G+2];
                float4 oa, ob, oc;
                chain_step(va.x, va.y, va.z, s); oa.x=s.t[0]; oa.y=s.t[1]; oa.z=s.t[2];
                chain_step(va.w, vb.x, vb.y, s); oa.w=s.t[0]; ob.x=s.t[1]; ob.y=s.t[2];
                chain_step(vb.z, vb.w, vc.x, s); ob.z=s.t[0]; ob.w=s.t[1]; oc.x=s.t[2];
                chain_step(vc.y, vc.z, vc.w, s); oc.y=s.t[0]; oc.z=s.t[1]; oc.w=s.t[2];
                row4[3*G] = oa; row4[3*G+1] = ob; row4[3*G+2] = oc;
            }
        } else {
            int lim = n - base;
            float* col = st + tid * ROWF;
            for (int k = 0; k < lim; k++) {
                chain_step(col[3*k], col[3*k+1], col[3*k+2], s);
                col[3*k]   = s.t[0];
                col[3*k+1] = s.t[1];
                col[3*k+2] = s.t[2];
            }
        }
    }
    __syncthreads();

    float* gout = out + 9 + tile0;
    if (nfl == TILE_F) {
        // head: floats 0..2 (row 0, q 0..2); tail: float 9215 (row 191, q 47)
        if (tid < 3) gout[tid] = st[tid];
        if (tid == 3) gout[TILE_F-1] = st[(TPB-1)*ROWF + Q - 1];
        // body: float4 m covers floats 3+4m .. 6+4m; (gout+3) is 16B-aligned.
        // q0 = (4*tid+3) % 48 invariant (stride 768 = 16*48); j0 += 16.
        float4* g4 = (float4*)(gout + 3);
        int f0 = 3 + 4*tid;
        int q0 = f0 % Q, j0 = f0 / Q;
        bool wrap = (q0 == Q - 1);
#pragma unroll
        for (int it = 0; it < 12; it++) {
            int m = tid + it*TPB;
            if (it == 11 && m >= (TILE_F-4)/4) break;   // m < 2303
            const float* r = st + j0*ROWF + q0;
            float4 v;
            if (!wrap) { v.x = r[0]; v.y = r[1]; v.z = r[2]; v.w = r[3]; }
            else {
                const float* r2 = st + (j0+1)*ROWF;
                v.x = r[0]; v.y = r2[0]; v.z = r2[1]; v.w = r2[2];
            }
            g4[m] = v;
            j0 += 16;
        }
    } else {
        int q0 = tid % Q, j0 = tid / Q;
        for (int f = tid; f < nfl; f += TPB) {
            gout[f] = st[j0*ROWF + q0];
            j0 += TPB/Q;
        }
    }
}

extern "C" void kernel_launch(void* const* d_in, const int* in_sizes, int n_in,
                              void* d_out, int out_size) {
    const float* inner = (const float*)d_in[0];
    const float* mc    = (const float*)d_in[2];
    float* out = (float*)d_out;
    int n = in_sizes[0] / 3;
    int nchunks = (n + C1 - 1) / C1;              // 187500
    int nblocks = (nchunks + TPB - 1) / TPB;      // 977  (<= 1024)

    k1_chunks<<<nblocks, TPB>>>(inner, n, nchunks);
    k2_scan<<<1, 1024>>>(nblocks, mc, out);
    k3_emit<<<nblocks, TPB>>>(inner, n, nchunks, out);
}